// round 14
// baseline (speedup 1.0000x reference)
#include <cuda_runtime.h>
#include <cuda_bf16.h>
#include <cuda_fp16.h>
#include <math.h>
#include <stdint.h>

#define H        512
#define NDRONES  16384
#define NPAIRS   131072

#define NCH      8          // K chunks of 64 (pair)
#define A64      16384      // 128 rows x 64k fp16
#define B64      32768      // 256 rows x 64k fp16
#define STAGE_UV 98304      // per uv stage: 2xA64 + 2xB64 (K=128)
#define B_TILE_P 65536      // pair B: 512 rows x 64k fp16

// ---------------- device scratch ---------------------------------------------
__device__ __align__(128) char g_ET[(size_t)128 * NCH * A64];   // E fp16 tiles (16MB)
__device__ __align__(128) char g_BU[(size_t)4 * NCH * B64];     // ABcomb^T fp16 tiles (1MB)
__device__ __align__(128) char g_BP[(size_t)NCH * B_TILE_P];    // W1d^T fp16 tiles (512KB)
__device__ float g_UV[(size_t)NDRONES * 2 * H];                 // [U(512)|V(512)] per drone

// ---------------- helpers ----------------------------------------------------
__device__ __forceinline__ uint32_t smem_u32(const void* p) {
    uint32_t a;
    asm("{ .reg .u64 t; cvta.to.shared.u64 t, %1; cvt.u32.u64 %0, t; }" : "=r"(a) : "l"(p));
    return a;
}
#define SW128(o) ((o) ^ (((o) >> 3) & 0x70))

__device__ __forceinline__ void ldsm_x4(uint32_t* r, uint32_t addr) {
    asm volatile("ldmatrix.sync.aligned.m8n8.x4.shared.b16 {%0,%1,%2,%3}, [%4];"
        : "=r"(r[0]), "=r"(r[1]), "=r"(r[2]), "=r"(r[3]) : "r"(addr));
}
__device__ __forceinline__ void mma_f16(float* c, const uint32_t* a, const uint32_t* b) {
    asm volatile("mma.sync.aligned.m16n8k16.row.col.f32.f16.f16.f32 "
        "{%0,%1,%2,%3}, {%4,%5,%6,%7}, {%8,%9}, {%0,%1,%2,%3};"
        : "+f"(c[0]), "+f"(c[1]), "+f"(c[2]), "+f"(c[3])
        : "r"(a[0]), "r"(a[1]), "r"(a[2]), "r"(a[3]), "r"(b[0]), "r"(b[1]));
}

#define MBARRIER_INIT(mbar, cnt) \
    asm volatile("mbarrier.init.shared.b64 [%0], %1;" :: "r"((uint32_t)(mbar)), "r"((uint32_t)(cnt)) : "memory")
#define MBARRIER_EXPECT_TX(mbar, tx) \
    asm volatile("mbarrier.arrive.expect_tx.shared.b64 _, [%0], %1;" :: "r"((uint32_t)(mbar)), "r"((uint32_t)(tx)) : "memory")
#define MBARRIER_WAIT_PARITY(mbar, parity) do { \
    uint32_t _m = (uint32_t)(mbar); uint32_t _p = (uint32_t)(parity); uint32_t _d; \
    asm volatile("{\n\t.reg .pred p;\n\tmbarrier.try_wait.parity.acquire.cta.shared::cta.b64 p, [%1], %2;\n\tselp.b32 %0,1,0,p;\n\t}" \
        : "=r"(_d) : "r"(_m), "r"(_p) : "memory"); \
    if (!_d) { \
        asm volatile("{\n\t.reg .pred P1;\n\tWL_%=:\n\tmbarrier.try_wait.parity.acquire.cta.shared::cta.b64 P1, [%0], %1, 0x989680;\n\t@P1 bra.uni WD_%=;\n\tbra.uni WL_%=;\n\tWD_%=:\n\t}" \
            :: "r"(_m), "r"(_p) : "memory"); \
    } } while (0)
#define FENCE_PROXY_ASYNC() asm volatile("fence.proxy.async.shared::cta;" ::: "memory")

__device__ __forceinline__ void bulk_g2s(uint32_t dst, const void* src, uint32_t bytes, uint32_t mbar) {
    asm volatile("cp.async.bulk.shared::cluster.global.mbarrier::complete_tx::bytes [%0], [%1], %2, [%3];"
        :: "r"(dst), "l"(src), "r"(bytes), "r"(mbar) : "memory");
}

// ---------------- SMEM layouts -----------------------------------------------
// uv: 2 stages of 96KB at 0/98304; epilogue C (133120B) reuses from 0
#define UV_MB     196608
#define SMEM_UV   197120
#define CSTRIDE_U 260
// pair: A 2x8K at 0/8192, B ring 3x64K at 16384
#define PA0       0
#define PA1       8192
#define PBB       16384
#define P_MB      212992
#define P_SRC     213056
#define P_DST     213312
#define P_B1      213568
#define P_W2      215616
#define SMEM_PAIR 217664
#define CSTRIDE_P 516

// ---------------- prep kernels (fp16, unchanged) -----------------------------
__global__ void prep_BP16(const float* __restrict__ W1) {   // 512 rows x 64k fp16
    extern __shared__ char bsm[];   // 64KB
    int t = threadIdx.x, ch = blockIdx.x;
    int k0 = ch * 64;
#pragma unroll
    for (int rr = 0; rr < 2; ++rr) {
        int n = rr * 256 + t;
#pragma unroll 4
        for (int i = 0; i < 64; ++i) {
            float v = W1[(size_t)(3 * H + k0 + i) * H + n];
            *(__half*)(bsm + SW128((uint32_t)(n * 128 + i * 2))) = __float2half_rn(v);
        }
    }
    __syncthreads();
    uint4* dst = (uint4*)(g_BP + (size_t)ch * B_TILE_P);
    const uint4* s4 = (const uint4*)bsm;
#pragma unroll
    for (int j = 0; j < 16; ++j) dst[t * 16 + j] = s4[t * 16 + j];
}

__global__ void prep_BU16(const float* __restrict__ W1) {   // 256 rows x 64k fp16
    extern __shared__ char bsm[];   // 32KB
    int t = threadIdx.x, ch = blockIdx.x, nb = blockIdx.y;
    int k0 = ch * 64;
    int ng = nb * 256 + t;
    bool isv = ng >= H;
    int nn = ng & (H - 1);
#pragma unroll 4
    for (int i = 0; i < 64; ++i) {
        int k = k0 + i;
        float wc = W1[(size_t)(2 * H + k) * H + nn];
        float v = isv ? (W1[(size_t)(H + k) * H + nn] + wc)
                      : (W1[(size_t)k * H + nn] - wc);
        *(__half*)(bsm + SW128((uint32_t)(t * 128 + i * 2))) = __float2half_rn(v);
    }
    __syncthreads();
    uint4* dst = (uint4*)(g_BU + ((size_t)nb * NCH + ch) * B64);
    const uint4* s4 = (const uint4*)bsm;
#pragma unroll
    for (int j = 0; j < 8; ++j) dst[t * 8 + j] = s4[t * 8 + j];
}

__global__ void prep_ET16(const float* __restrict__ E) {    // 128 rows x 64k fp16 single
    __shared__ __align__(16) char esm[A64];
    int t = threadIdx.x, ch = blockIdx.x, mb = blockIdx.y;
    int k0 = ch * 64, m0 = mb * 128;
#pragma unroll 4
    for (int i = 0; i < 32; ++i) {
        int idx = i * 256 + t;
        int k_l = idx & 63, r = idx >> 6;
        float v = E[(size_t)(m0 + r) * H + k0 + k_l];
        *(__half*)(esm + SW128((uint32_t)(r * 128 + k_l * 2))) = __float2half_rn(v);
    }
    __syncthreads();
    uint4* dst = (uint4*)(g_ET + ((size_t)mb * NCH + ch) * A64);
    const uint4* s4 = (const uint4*)esm;
#pragma unroll
    for (int j = 0; j < 4; ++j) dst[t * 4 + j] = s4[t * 4 + j];
}

// ---------------- UV GEMM: K-chunk 128 (unchanged R13) -----------------------
__global__ void __launch_bounds__(256, 1) uv_mma_k() {
    extern __shared__ __align__(1024) char smem[];
    uint32_t sb = smem_u32(smem);
    int t = threadIdx.x, lane = t & 31, w = t >> 5;
    int wm = w >> 2, wn = w & 3;          // warp tile 64x64
    int mb = blockIdx.x, nb = blockIdx.y;

    if (t == 0) { MBARRIER_INIT(sb + UV_MB, 1); MBARRIER_INIT(sb + UV_MB + 8, 1); }
    __syncthreads();
    const char* gA = g_ET + (size_t)mb * NCH * A64;
    const char* gB = g_BU + (size_t)nb * NCH * B64;
    if (t == 0) {
#pragma unroll
        for (int s = 0; s < 2; ++s) {
            int cc = 2 * s;
            MBARRIER_EXPECT_TX(sb + UV_MB + s * 8, STAGE_UV);
            bulk_g2s(sb + s * STAGE_UV,          gA + (size_t)cc * A64,        A64, sb + UV_MB + s * 8);
            bulk_g2s(sb + s * STAGE_UV + A64,    gA + (size_t)(cc + 1) * A64,  A64, sb + UV_MB + s * 8);
            bulk_g2s(sb + s * STAGE_UV + 32768,  gB + (size_t)cc * B64,        B64, sb + UV_MB + s * 8);
            bulk_g2s(sb + s * STAGE_UV + 65536,  gB + (size_t)(cc + 1) * B64,  B64, sb + UV_MB + s * 8);
        }
    }

    uint32_t arx = (lane & 7) * 16, selA = (lane >> 4) * 16;
    uint32_t brx = (lane & 7) * 16, selB = ((lane >> 3) & 1) * 16;
    uint32_t aoff[4];
#pragma unroll
    for (int mt = 0; mt < 4; ++mt)
        aoff[mt] = (uint32_t)(wm * 64 + mt * 16 + (lane & 15)) * 128;
    uint32_t boffB = (uint32_t)(wn * 64 + ((lane >> 4) & 1) * 8 + (lane & 7)) * 128;

    float c[4][8][4];
#pragma unroll
    for (int a = 0; a < 4; ++a)
#pragma unroll
        for (int b = 0; b < 8; ++b)
#pragma unroll
            for (int d = 0; d < 4; ++d) c[a][b][d] = 0.f;

    int ph0 = 0, ph1 = 0;
    for (int c2 = 0; c2 < 4; ++c2) {
        int s = c2 & 1;
        if (s == 0) { MBARRIER_WAIT_PARITY(sb + UV_MB, ph0); ph0 ^= 1; }
        else        { MBARRIER_WAIT_PARITY(sb + UV_MB + 8, ph1); ph1 ^= 1; }
#pragma unroll
        for (int half = 0; half < 2; ++half) {
            uint32_t As = sb + s * STAGE_UV + half * A64;
            uint32_t Bs = sb + s * STAGE_UV + 32768 + half * B64;
#pragma unroll
            for (int kh = 0; kh < 4; ++kh) {
                uint32_t kk = kh * 32;
                uint32_t ah[4][4];
#pragma unroll
                for (int mt = 0; mt < 4; ++mt)
                    ldsm_x4(ah[mt], As + aoff[mt] + ((kk + selA) ^ arx));
#pragma unroll
                for (int ntp = 0; ntp < 4; ++ntp) {
                    uint32_t bb[4];
                    ldsm_x4(bb, Bs + boffB + ntp * 2048 + ((kk + selB) ^ brx));
#pragma unroll
                    for (int mt = 0; mt < 4; ++mt) {
                        mma_f16(c[mt][2 * ntp],     ah[mt], bb);
                        mma_f16(c[mt][2 * ntp + 1], ah[mt], bb + 2);
                    }
                }
            }
        }
        __syncthreads();
        if (t == 0 && c2 + 2 < 4) {
            FENCE_PROXY_ASYNC();
            int cc = 2 * (c2 + 2);
            MBARRIER_EXPECT_TX(sb + UV_MB + s * 8, STAGE_UV);
            bulk_g2s(sb + s * STAGE_UV,          gA + (size_t)cc * A64,        A64, sb + UV_MB + s * 8);
            bulk_g2s(sb + s * STAGE_UV + A64,    gA + (size_t)(cc + 1) * A64,  A64, sb + UV_MB + s * 8);
            bulk_g2s(sb + s * STAGE_UV + 32768,  gB + (size_t)cc * B64,        B64, sb + UV_MB + s * 8);
            bulk_g2s(sb + s * STAGE_UV + 65536,  gB + (size_t)(cc + 1) * B64,  B64, sb + UV_MB + s * 8);
        }
    }

    float* Cs = (float*)smem;
#pragma unroll
    for (int mt = 0; mt < 4; ++mt)
#pragma unroll
        for (int nt = 0; nt < 8; ++nt) {
            int r  = wm * 64 + mt * 16 + (lane >> 2);
            int c0 = wn * 64 + nt * 8 + (lane & 3) * 2;
            *(float2*)(Cs + r * CSTRIDE_U + c0)       = make_float2(c[mt][nt][0], c[mt][nt][1]);
            *(float2*)(Cs + (r + 8) * CSTRIDE_U + c0) = make_float2(c[mt][nt][2], c[mt][nt][3]);
        }
    __syncthreads();
    int r = t >> 1, half = t & 1;
    float* dst = g_UV + (size_t)(mb * 128 + r) * (2 * H) + nb * 256 + half * 128;
    const float* srow = Cs + r * CSTRIDE_U + half * 128;
#pragma unroll
    for (int j = 0; j < 128; j += 4)
        *(float4*)(dst + j) = *(const float4*)(srow + j);
}

// ---------------- pair GEMM: single sync/chunk, UNROLLED 3-ring --------------
__global__ void __launch_bounds__(256, 1) pair_mma_k(
    const float* __restrict__ E, const int* __restrict__ rel,
    const float* __restrict__ b1, const float* __restrict__ W2,
    const float* __restrict__ b2, float* __restrict__ out)
{
    extern __shared__ __align__(1024) char smem[];
    uint32_t sb = smem_u32(smem);
    int t = threadIdx.x, lane = t & 31, w = t >> 5;       // w 0..7
    int wn = w;                                           // 1x8 grid, warp tile 64x64
    int bx = blockIdx.x;
    int p0 = bx * 64;

    int* ssrc = (int*)(smem + P_SRC);
    int* sdst = (int*)(smem + P_DST);
    float* b1s = (float*)(smem + P_B1);
    float* w2s = (float*)(smem + P_W2);
    if (t < 64) {
        ssrc[t] = rel[(size_t)(p0 + t) * 2 + 0];
        sdst[t] = rel[(size_t)(p0 + t) * 2 + 1];
    }
    b1s[t] = b1[t];       b1s[256 + t] = b1[256 + t];
    w2s[t] = W2[t];       w2s[256 + t] = W2[256 + t];
    if (t == 0) {
        MBARRIER_INIT(sb + P_MB, 1);
        MBARRIER_INIT(sb + P_MB + 8, 1);
        MBARRIER_INIT(sb + P_MB + 16, 1);
    }
    __syncthreads();

    // initial fills: chunks 0,1 -> buffers 0,1
    if (t == 0) {
#pragma unroll
        for (int s = 0; s < 2; ++s) {
            MBARRIER_EXPECT_TX(sb + P_MB + s * 8, B_TILE_P);
            bulk_g2s(sb + PBB + s * B_TILE_P, g_BP + (size_t)s * B_TILE_P, B_TILE_P, sb + P_MB + s * 8);
        }
    }

    // line-coalesced gather: 16 lanes per row, 4 passes (R13-verified).
    int row16 = t >> 4, seg = t & 15;
    const float* Sp[4];
    const float* Dp[4];
    uint32_t asw[4];
#pragma unroll
    for (int pass = 0; pass < 4; ++pass) {
        int r = pass * 16 + row16;
        Sp[pass] = E + (size_t)ssrc[r] * H + seg * 4;
        Dp[pass] = E + (size_t)sdst[r] * H + seg * 4;
        asw[pass] = SW128((uint32_t)(r * 128 + seg * 8));
    }

    uint32_t arx = (lane & 7) * 16, selA = (lane >> 4) * 16;
    uint32_t brx = (lane & 7) * 16, selB = ((lane >> 3) & 1) * 16;
    uint32_t aoff[4];
#pragma unroll
    for (int mt = 0; mt < 4; ++mt)
        aoff[mt] = (uint32_t)(mt * 16 + (lane & 15)) * 128;          // M=64: 4 tiles of 16
    uint32_t boffB = (uint32_t)(wn * 64 + ((lane >> 4) & 1) * 8 + (lane & 7)) * 128;

    float c[4][8][4];
#pragma unroll
    for (int a = 0; a < 4; ++a)
#pragma unroll
        for (int b = 0; b < 8; ++b)
#pragma unroll
            for (int d = 0; d < 4; ++d) c[a][b][d] = 0.f;

    // prefetch chunk 0: one float4 per matrix per pass
    float4 ps[4], pd[4];
#pragma unroll
    for (int j = 0; j < 4; ++j) {
        ps[j] = *(const float4*)(Sp[j]);
        pd[j] = *(const float4*)(Dp[j]);
    }

    // FULLY UNROLLED mainloop: all buffer indices / parities are literals.
#pragma unroll
    for (int ch = 0; ch < NCH; ++ch) {
        const int s     = ch & 1;           // A buffer
        const int bbuf  = ch % 3;           // B read buffer
        const int bpar  = (ch / 3) & 1;     // wait parity for that buffer's fill
        const int bnext = (ch + 2) % 3;     // B refill target
        // ---- stage A(ch) from prefetched regs (overlaps other warps' MMA(ch-1)) ----
        {
            char* Ab = smem + (s ? PA1 : PA0);
#pragma unroll
            for (int j = 0; j < 4; ++j) {
                float pr0 = ps[j].x * pd[j].x;
                float pr1 = ps[j].y * pd[j].y;
                float pr2 = ps[j].z * pd[j].z;
                float pr3 = ps[j].w * pd[j].w;
                __half2 h0 = __floats2half2_rn(pr0, pr1);
                __half2 h1 = __floats2half2_rn(pr2, pr3);
                *(uint2*)(Ab + asw[j]) = make_uint2(
                    *reinterpret_cast<uint32_t*>(&h0), *reinterpret_cast<uint32_t*>(&h1));
            }
        }
        // ---- prefetch chunk ch+1 ----
        if (ch + 1 < NCH) {
            const int k0 = (ch + 1) * 64;
#pragma unroll
            for (int j = 0; j < 4; ++j) {
                ps[j] = *(const float4*)(Sp[j] + k0);
                pd[j] = *(const float4*)(Dp[j] + k0);
            }
        }
        // ---- wait B(ch) [literal mbar addr + parity], single CTA sync ----
        MBARRIER_WAIT_PARITY(sb + P_MB + bbuf * 8, bpar);
        __syncthreads();
        // ---- refill chunk ch+2 into literal buffer bnext (prior reader done) ----
        if (t == 0 && ch + 2 < NCH) {
            FENCE_PROXY_ASYNC();
            MBARRIER_EXPECT_TX(sb + P_MB + bnext * 8, B_TILE_P);
            bulk_g2s(sb + PBB + bnext * B_TILE_P, g_BP + (size_t)(ch + 2) * B_TILE_P, B_TILE_P, sb + P_MB + bnext * 8);
        }
        // ---- MMA(ch): single term, warp tile 64x64 ----
        const uint32_t As = sb + (s ? PA1 : PA0);
        const uint32_t Bs = sb + PBB + bbuf * B_TILE_P;
#pragma unroll
        for (int kh = 0; kh < 4; ++kh) {
            uint32_t kk = kh * 32;
            uint32_t ah[4][4];
#pragma unroll
            for (int mt = 0; mt < 4; ++mt)
                ldsm_x4(ah[mt], As + aoff[mt] + ((kk + selA) ^ arx));
#pragma unroll
            for (int ntp = 0; ntp < 4; ++ntp) {
                uint32_t bb[4];
                ldsm_x4(bb, Bs + boffB + ntp * 2048 + ((kk + selB) ^ brx));
#pragma unroll
                for (int mt = 0; mt < 4; ++mt) {
                    mma_f16(c[mt][2 * ntp],     ah[mt], bb);
                    mma_f16(c[mt][2 * ntp + 1], ah[mt], bb + 2);
                }
            }
        }
    }

    __syncthreads();   // all MMA done before Cs overwrites A/B buffers

    // C -> smem (64 rows x 512 cols)
    float* Cs = (float*)smem;
#pragma unroll
    for (int mt = 0; mt < 4; ++mt)
#pragma unroll
        for (int nt = 0; nt < 8; ++nt) {
            int r  = mt * 16 + (lane >> 2);
            int c0 = wn * 64 + nt * 8 + (lane & 3) * 2;
            *(float2*)(Cs + r * CSTRIDE_P + c0)       = make_float2(c[mt][nt][0], c[mt][nt][1]);
            *(float2*)(Cs + (r + 8) * CSTRIDE_P + c0) = make_float2(c[mt][nt][2], c[mt][nt][3]);
        }
    __syncthreads();

    // epilogue: z = sum relu(C + U[src] + V[dst] + b1) * W2 ; out = sigmoid(z+b2)
    {
        int r = t >> 2, q = t & 3;
        const float* crow = Cs + r * CSTRIDE_P + q * 128;
        const float* urow = g_UV + (size_t)ssrc[r] * (2 * H) + q * 128;
        const float* vrow = g_UV + (size_t)sdst[r] * (2 * H) + H + q * 128;
        float partial = 0.f;
#pragma unroll
        for (int j = 0; j < 128; j += 4) {
            float4 cc = *(const float4*)(crow + j);
            float4 u  = *(const float4*)(urow + j);
            float4 v  = *(const float4*)(vrow + j);
            int n = q * 128 + j;
            float h0 = cc.x + u.x + v.x + b1s[n + 0];
            float h1 = cc.y + u.y + v.y + b1s[n + 1];
            float h2 = cc.z + u.z + v.z + b1s[n + 2];
            float h3 = cc.w + u.w + v.w + b1s[n + 3];
            partial = fmaf(fmaxf(h0, 0.f), w2s[n + 0], partial);
            partial = fmaf(fmaxf(h1, 0.f), w2s[n + 1], partial);
            partial = fmaf(fmaxf(h2, 0.f), w2s[n + 2], partial);
            partial = fmaf(fmaxf(h3, 0.f), w2s[n + 3], partial);
        }
        partial += __shfl_xor_sync(0xffffffffu, partial, 1);
        partial += __shfl_xor_sync(0xffffffffu, partial, 2);
        if (q == 0) {
            float z = partial + b2[0];
            out[p0 + r] = 1.f / (1.f + expf(-z));
        }
    }
}

// ---------------- launch -----------------------------------------------------
extern "C" void kernel_launch(void* const* d_in, const int* in_sizes, int n_in,
                              void* d_out, int out_size) {
    const float* E   = (const float*)d_in[1];
    const int*   rel = (const int*)  d_in[2];
    const float* W1  = (const float*)d_in[3];
    const float* b1  = (const float*)d_in[4];
    const float* W2  = (const float*)d_in[5];
    const float* b2  = (const float*)d_in[6];
    float* out = (float*)d_out;

    cudaFuncSetAttribute(prep_BP16, cudaFuncAttributeMaxDynamicSharedMemorySize, B_TILE_P);
    cudaFuncSetAttribute(prep_BU16, cudaFuncAttributeMaxDynamicSharedMemorySize, B64);
    cudaFuncSetAttribute(uv_mma_k, cudaFuncAttributeMaxDynamicSharedMemorySize, SMEM_UV);
    cudaFuncSetAttribute(pair_mma_k, cudaFuncAttributeMaxDynamicSharedMemorySize, SMEM_PAIR);

    prep_BP16<<<NCH, 256, B_TILE_P>>>(W1);
    prep_BU16<<<dim3(NCH, 4), 256, B64>>>(W1);
    prep_ET16<<<dim3(NCH, 128), 256>>>(E);
    uv_mma_k<<<dim3(128, 4), 256, SMEM_UV>>>();
    pair_mma_k<<<NPAIRS / 64, 256, SMEM_PAIR>>>(E, rel, b1, W2, b2, out);
}

// round 15
// speedup vs baseline: 1.3427x; 1.3427x over previous
#include <cuda_runtime.h>
#include <cuda_bf16.h>
#include <cuda_fp16.h>
#include <math.h>
#include <stdint.h>

#define H        512
#define NDRONES  16384
#define NPAIRS   131072

#define NCH      8          // K chunks of 64 (pair)
#define A64      16384      // 128 rows x 64k fp16
#define B64      32768      // 256 rows x 64k fp16
#define STAGE_UV 98304      // per uv stage: 2xA64 + 2xB64 (K=128)
#define B_TILE_P 65536      // pair B: 512 rows x 64k fp16

// ---------------- device scratch ---------------------------------------------
__device__ __align__(128) char g_ET[(size_t)128 * NCH * A64];   // E fp16 tiles (16MB)
__device__ __align__(128) char g_BU[(size_t)4 * NCH * B64];     // ABcomb^T fp16 tiles (1MB)
__device__ __align__(128) char g_BP[(size_t)NCH * B_TILE_P];    // W1d^T fp16 tiles (512KB)
__device__ __half g_UVh[(size_t)NDRONES * 2 * H];               // fp16 [U(512)|V(512)] per drone (32MB)

// ---------------- helpers ----------------------------------------------------
__device__ __forceinline__ uint32_t smem_u32(const void* p) {
    uint32_t a;
    asm("{ .reg .u64 t; cvta.to.shared.u64 t, %1; cvt.u32.u64 %0, t; }" : "=r"(a) : "l"(p));
    return a;
}
#define SW128(o) ((o) ^ (((o) >> 3) & 0x70))

__device__ __forceinline__ void ldsm_x4(uint32_t* r, uint32_t addr) {
    asm volatile("ldmatrix.sync.aligned.m8n8.x4.shared.b16 {%0,%1,%2,%3}, [%4];"
        : "=r"(r[0]), "=r"(r[1]), "=r"(r[2]), "=r"(r[3]) : "r"(addr));
}
__device__ __forceinline__ void mma_f16(float* c, const uint32_t* a, const uint32_t* b) {
    asm volatile("mma.sync.aligned.m16n8k16.row.col.f32.f16.f16.f32 "
        "{%0,%1,%2,%3}, {%4,%5,%6,%7}, {%8,%9}, {%0,%1,%2,%3};"
        : "+f"(c[0]), "+f"(c[1]), "+f"(c[2]), "+f"(c[3])
        : "r"(a[0]), "r"(a[1]), "r"(a[2]), "r"(a[3]), "r"(b[0]), "r"(b[1]));
}

#define MBARRIER_INIT(mbar, cnt) \
    asm volatile("mbarrier.init.shared.b64 [%0], %1;" :: "r"((uint32_t)(mbar)), "r"((uint32_t)(cnt)) : "memory")
#define MBARRIER_EXPECT_TX(mbar, tx) \
    asm volatile("mbarrier.arrive.expect_tx.shared.b64 _, [%0], %1;" :: "r"((uint32_t)(mbar)), "r"((uint32_t)(tx)) : "memory")
#define MBARRIER_WAIT_PARITY(mbar, parity) do { \
    uint32_t _m = (uint32_t)(mbar); uint32_t _p = (uint32_t)(parity); uint32_t _d; \
    asm volatile("{\n\t.reg .pred p;\n\tmbarrier.try_wait.parity.acquire.cta.shared::cta.b64 p, [%1], %2;\n\tselp.b32 %0,1,0,p;\n\t}" \
        : "=r"(_d) : "r"(_m), "r"(_p) : "memory"); \
    if (!_d) { \
        asm volatile("{\n\t.reg .pred P1;\n\tWL_%=:\n\tmbarrier.try_wait.parity.acquire.cta.shared::cta.b64 P1, [%0], %1, 0x989680;\n\t@P1 bra.uni WD_%=;\n\tbra.uni WL_%=;\n\tWD_%=:\n\t}" \
            :: "r"(_m), "r"(_p) : "memory"); \
    } } while (0)
#define FENCE_PROXY_ASYNC() asm volatile("fence.proxy.async.shared::cta;" ::: "memory")

__device__ __forceinline__ void bulk_g2s(uint32_t dst, const void* src, uint32_t bytes, uint32_t mbar) {
    asm volatile("cp.async.bulk.shared::cluster.global.mbarrier::complete_tx::bytes [%0], [%1], %2, [%3];"
        :: "r"(dst), "l"(src), "r"(bytes), "r"(mbar) : "memory");
}

// ---------------- SMEM layouts -----------------------------------------------
// uv: 2 stages of 96KB at 0/98304; epilogue C (133120B) reuses from 0
#define UV_MB     196608
#define SMEM_UV   197120
#define CSTRIDE_U 260
// pair (R13 layout): A 2x8K at 0/8192, B 2x64K at 16384/81920
#define PA0       0
#define PA1       8192
#define PB0       16384
#define P_MB      163840
#define P_SRC     163904
#define P_DST     164160
#define P_B1      164416
#define P_W2      166464
#define SMEM_PAIR 168512
#define CSTRIDE_P 516

// ---------------- prep kernels (fp16, unchanged) -----------------------------
__global__ void prep_BP16(const float* __restrict__ W1) {   // 512 rows x 64k fp16
    extern __shared__ char bsm[];   // 64KB
    int t = threadIdx.x, ch = blockIdx.x;
    int k0 = ch * 64;
#pragma unroll
    for (int rr = 0; rr < 2; ++rr) {
        int n = rr * 256 + t;
#pragma unroll 4
        for (int i = 0; i < 64; ++i) {
            float v = W1[(size_t)(3 * H + k0 + i) * H + n];
            *(__half*)(bsm + SW128((uint32_t)(n * 128 + i * 2))) = __float2half_rn(v);
        }
    }
    __syncthreads();
    uint4* dst = (uint4*)(g_BP + (size_t)ch * B_TILE_P);
    const uint4* s4 = (const uint4*)bsm;
#pragma unroll
    for (int j = 0; j < 16; ++j) dst[t * 16 + j] = s4[t * 16 + j];
}

__global__ void prep_BU16(const float* __restrict__ W1) {   // 256 rows x 64k fp16
    extern __shared__ char bsm[];   // 32KB
    int t = threadIdx.x, ch = blockIdx.x, nb = blockIdx.y;
    int k0 = ch * 64;
    int ng = nb * 256 + t;
    bool isv = ng >= H;
    int nn = ng & (H - 1);
#pragma unroll 4
    for (int i = 0; i < 64; ++i) {
        int k = k0 + i;
        float wc = W1[(size_t)(2 * H + k) * H + nn];
        float v = isv ? (W1[(size_t)(H + k) * H + nn] + wc)
                      : (W1[(size_t)k * H + nn] - wc);
        *(__half*)(bsm + SW128((uint32_t)(t * 128 + i * 2))) = __float2half_rn(v);
    }
    __syncthreads();
    uint4* dst = (uint4*)(g_BU + ((size_t)nb * NCH + ch) * B64);
    const uint4* s4 = (const uint4*)bsm;
#pragma unroll
    for (int j = 0; j < 8; ++j) dst[t * 8 + j] = s4[t * 8 + j];
}

__global__ void prep_ET16(const float* __restrict__ E) {    // 128 rows x 64k fp16 single
    __shared__ __align__(16) char esm[A64];
    int t = threadIdx.x, ch = blockIdx.x, mb = blockIdx.y;
    int k0 = ch * 64, m0 = mb * 128;
#pragma unroll 4
    for (int i = 0; i < 32; ++i) {
        int idx = i * 256 + t;
        int k_l = idx & 63, r = idx >> 6;
        float v = E[(size_t)(m0 + r) * H + k0 + k_l];
        *(__half*)(esm + SW128((uint32_t)(r * 128 + k_l * 2))) = __float2half_rn(v);
    }
    __syncthreads();
    uint4* dst = (uint4*)(g_ET + ((size_t)mb * NCH + ch) * A64);
    const uint4* s4 = (const uint4*)esm;
#pragma unroll
    for (int j = 0; j < 4; ++j) dst[t * 4 + j] = s4[t * 4 + j];
}

// ---------------- UV GEMM: K-chunk 128 (R13) + fp16 writeback ----------------
__global__ void __launch_bounds__(256, 1) uv_mma_k() {
    extern __shared__ __align__(1024) char smem[];
    uint32_t sb = smem_u32(smem);
    int t = threadIdx.x, lane = t & 31, w = t >> 5;
    int wm = w >> 2, wn = w & 3;          // warp tile 64x64
    int mb = blockIdx.x, nb = blockIdx.y;

    if (t == 0) { MBARRIER_INIT(sb + UV_MB, 1); MBARRIER_INIT(sb + UV_MB + 8, 1); }
    __syncthreads();
    const char* gA = g_ET + (size_t)mb * NCH * A64;
    const char* gB = g_BU + (size_t)nb * NCH * B64;
    if (t == 0) {
#pragma unroll
        for (int s = 0; s < 2; ++s) {
            int cc = 2 * s;
            MBARRIER_EXPECT_TX(sb + UV_MB + s * 8, STAGE_UV);
            bulk_g2s(sb + s * STAGE_UV,          gA + (size_t)cc * A64,        A64, sb + UV_MB + s * 8);
            bulk_g2s(sb + s * STAGE_UV + A64,    gA + (size_t)(cc + 1) * A64,  A64, sb + UV_MB + s * 8);
            bulk_g2s(sb + s * STAGE_UV + 32768,  gB + (size_t)cc * B64,        B64, sb + UV_MB + s * 8);
            bulk_g2s(sb + s * STAGE_UV + 65536,  gB + (size_t)(cc + 1) * B64,  B64, sb + UV_MB + s * 8);
        }
    }

    uint32_t arx = (lane & 7) * 16, selA = (lane >> 4) * 16;
    uint32_t brx = (lane & 7) * 16, selB = ((lane >> 3) & 1) * 16;
    uint32_t aoff[4];
#pragma unroll
    for (int mt = 0; mt < 4; ++mt)
        aoff[mt] = (uint32_t)(wm * 64 + mt * 16 + (lane & 15)) * 128;
    uint32_t boffB = (uint32_t)(wn * 64 + ((lane >> 4) & 1) * 8 + (lane & 7)) * 128;

    float c[4][8][4];
#pragma unroll
    for (int a = 0; a < 4; ++a)
#pragma unroll
        for (int b = 0; b < 8; ++b)
#pragma unroll
            for (int d = 0; d < 4; ++d) c[a][b][d] = 0.f;

    int ph0 = 0, ph1 = 0;
    for (int c2 = 0; c2 < 4; ++c2) {
        int s = c2 & 1;
        if (s == 0) { MBARRIER_WAIT_PARITY(sb + UV_MB, ph0); ph0 ^= 1; }
        else        { MBARRIER_WAIT_PARITY(sb + UV_MB + 8, ph1); ph1 ^= 1; }
#pragma unroll
        for (int half = 0; half < 2; ++half) {
            uint32_t As = sb + s * STAGE_UV + half * A64;
            uint32_t Bs = sb + s * STAGE_UV + 32768 + half * B64;
#pragma unroll
            for (int kh = 0; kh < 4; ++kh) {
                uint32_t kk = kh * 32;
                uint32_t ah[4][4];
#pragma unroll
                for (int mt = 0; mt < 4; ++mt)
                    ldsm_x4(ah[mt], As + aoff[mt] + ((kk + selA) ^ arx));
#pragma unroll
                for (int ntp = 0; ntp < 4; ++ntp) {
                    uint32_t bb[4];
                    ldsm_x4(bb, Bs + boffB + ntp * 2048 + ((kk + selB) ^ brx));
#pragma unroll
                    for (int mt = 0; mt < 4; ++mt) {
                        mma_f16(c[mt][2 * ntp],     ah[mt], bb);
                        mma_f16(c[mt][2 * ntp + 1], ah[mt], bb + 2);
                    }
                }
            }
        }
        __syncthreads();
        if (t == 0 && c2 + 2 < 4) {
            FENCE_PROXY_ASYNC();
            int cc = 2 * (c2 + 2);
            MBARRIER_EXPECT_TX(sb + UV_MB + s * 8, STAGE_UV);
            bulk_g2s(sb + s * STAGE_UV,          gA + (size_t)cc * A64,        A64, sb + UV_MB + s * 8);
            bulk_g2s(sb + s * STAGE_UV + A64,    gA + (size_t)(cc + 1) * A64,  A64, sb + UV_MB + s * 8);
            bulk_g2s(sb + s * STAGE_UV + 32768,  gB + (size_t)cc * B64,        B64, sb + UV_MB + s * 8);
            bulk_g2s(sb + s * STAGE_UV + 65536,  gB + (size_t)(cc + 1) * B64,  B64, sb + UV_MB + s * 8);
        }
    }

    float* Cs = (float*)smem;
#pragma unroll
    for (int mt = 0; mt < 4; ++mt)
#pragma unroll
        for (int nt = 0; nt < 8; ++nt) {
            int r  = wm * 64 + mt * 16 + (lane >> 2);
            int c0 = wn * 64 + nt * 8 + (lane & 3) * 2;
            *(float2*)(Cs + r * CSTRIDE_U + c0)       = make_float2(c[mt][nt][0], c[mt][nt][1]);
            *(float2*)(Cs + (r + 8) * CSTRIDE_U + c0) = make_float2(c[mt][nt][2], c[mt][nt][3]);
        }
    __syncthreads();
    int r = t >> 1, half = t & 1;
    __half* dst = g_UVh + (size_t)(mb * 128 + r) * (2 * H) + nb * 256 + half * 128;
    const float* srow = Cs + r * CSTRIDE_U + half * 128;
#pragma unroll
    for (int j = 0; j < 128; j += 8) {
        float4 a = *(const float4*)(srow + j);
        float4 b = *(const float4*)(srow + j + 4);
        __half2 h0 = __floats2half2_rn(a.x, a.y);
        __half2 h1 = __floats2half2_rn(a.z, a.w);
        __half2 h2 = __floats2half2_rn(b.x, b.y);
        __half2 h3 = __floats2half2_rn(b.z, b.w);
        *(uint4*)(dst + j) = make_uint4(
            *reinterpret_cast<uint32_t*>(&h0), *reinterpret_cast<uint32_t*>(&h1),
            *reinterpret_cast<uint32_t*>(&h2), *reinterpret_cast<uint32_t*>(&h3));
    }
}

// ---------------- pair GEMM: R13 structure, fp16 UV epilogue -----------------
__global__ void __launch_bounds__(256, 1) pair_mma_k(
    const float* __restrict__ E, const int* __restrict__ rel,
    const float* __restrict__ b1, const float* __restrict__ W2,
    const float* __restrict__ b2, float* __restrict__ out)
{
    extern __shared__ __align__(1024) char smem[];
    uint32_t sb = smem_u32(smem);
    int t = threadIdx.x, lane = t & 31, w = t >> 5;       // w 0..7
    int wn = w;                                           // 1x8 grid, warp tile 64x64
    int bx = blockIdx.x;
    int p0 = bx * 64;

    int* ssrc = (int*)(smem + P_SRC);
    int* sdst = (int*)(smem + P_DST);
    float* b1s = (float*)(smem + P_B1);
    float* w2s = (float*)(smem + P_W2);
    if (t < 64) {
        ssrc[t] = rel[(size_t)(p0 + t) * 2 + 0];
        sdst[t] = rel[(size_t)(p0 + t) * 2 + 1];
    }
    b1s[t] = b1[t];       b1s[256 + t] = b1[256 + t];
    w2s[t] = W2[t];       w2s[256 + t] = W2[256 + t];
    if (t == 0) { MBARRIER_INIT(sb + P_MB, 1); MBARRIER_INIT(sb + P_MB + 8, 1); }
    __syncthreads();

    if (t == 0) {
#pragma unroll
        for (int s = 0; s < 2; ++s) {
            MBARRIER_EXPECT_TX(sb + P_MB + s * 8, B_TILE_P);
            bulk_g2s(sb + PB0 + s * B_TILE_P, g_BP + (size_t)s * B_TILE_P, B_TILE_P, sb + P_MB + s * 8);
        }
    }

    // line-coalesced gather: 16 lanes per row, 4 passes (R13-verified).
    int row16 = t >> 4, seg = t & 15;
    const float* Sp[4];
    const float* Dp[4];
    uint32_t asw[4];
#pragma unroll
    for (int pass = 0; pass < 4; ++pass) {
        int r = pass * 16 + row16;
        Sp[pass] = E + (size_t)ssrc[r] * H + seg * 4;
        Dp[pass] = E + (size_t)sdst[r] * H + seg * 4;
        asw[pass] = SW128((uint32_t)(r * 128 + seg * 8));
    }

    uint32_t arx = (lane & 7) * 16, selA = (lane >> 4) * 16;
    uint32_t brx = (lane & 7) * 16, selB = ((lane >> 3) & 1) * 16;
    uint32_t aoff[4];
#pragma unroll
    for (int mt = 0; mt < 4; ++mt)
        aoff[mt] = (uint32_t)(mt * 16 + (lane & 15)) * 128;          // M=64: 4 tiles of 16
    uint32_t boffB = (uint32_t)(wn * 64 + ((lane >> 4) & 1) * 8 + (lane & 7)) * 128;

    float c[4][8][4];
#pragma unroll
    for (int a = 0; a < 4; ++a)
#pragma unroll
        for (int b = 0; b < 8; ++b)
#pragma unroll
            for (int d = 0; d < 4; ++d) c[a][b][d] = 0.f;

    // prefetch chunk 0: one float4 per matrix per pass
    float4 ps[4], pd[4];
#pragma unroll
    for (int j = 0; j < 4; ++j) {
        ps[j] = *(const float4*)(Sp[j]);
        pd[j] = *(const float4*)(Dp[j]);
    }

    int ph0 = 0, ph1 = 0;
    for (int ch = 0; ch < NCH; ++ch) {
        int s = ch & 1;
        // ---- stage A(ch) from prefetched regs: single fp16, STS.64 ----
        {
            char* Ab = smem + (s ? PA1 : PA0);
#pragma unroll
            for (int j = 0; j < 4; ++j) {
                float pr0 = ps[j].x * pd[j].x;
                float pr1 = ps[j].y * pd[j].y;
                float pr2 = ps[j].z * pd[j].z;
                float pr3 = ps[j].w * pd[j].w;
                __half2 h0 = __floats2half2_rn(pr0, pr1);
                __half2 h1 = __floats2half2_rn(pr2, pr3);
                *(uint2*)(Ab + asw[j]) = make_uint2(
                    *reinterpret_cast<uint32_t*>(&h0), *reinterpret_cast<uint32_t*>(&h1));
            }
        }
        // ---- prefetch chunk ch+1 (hidden under MMA) ----
        if (ch + 1 < NCH) {
            int k0 = (ch + 1) * 64;
#pragma unroll
            for (int j = 0; j < 4; ++j) {
                ps[j] = *(const float4*)(Sp[j] + k0);
                pd[j] = *(const float4*)(Dp[j] + k0);
            }
        }
        // ---- wait B(ch), sync A ----
        if (s == 0) { MBARRIER_WAIT_PARITY(sb + P_MB, ph0); ph0 ^= 1; }
        else        { MBARRIER_WAIT_PARITY(sb + P_MB + 8, ph1); ph1 ^= 1; }
        __syncthreads();
        // ---- MMA(ch): single term, warp tile 64x64 ----
        uint32_t As = sb + (s ? PA1 : PA0);
        uint32_t Bs = sb + PB0 + s * B_TILE_P;
#pragma unroll
        for (int kh = 0; kh < 4; ++kh) {
            uint32_t kk = kh * 32;
            uint32_t ah[4][4];
#pragma unroll
            for (int mt = 0; mt < 4; ++mt)
                ldsm_x4(ah[mt], As + aoff[mt] + ((kk + selA) ^ arx));
#pragma unroll
            for (int ntp = 0; ntp < 4; ++ntp) {
                uint32_t bb[4];
                ldsm_x4(bb, Bs + boffB + ntp * 2048 + ((kk + selB) ^ brx));
#pragma unroll
                for (int mt = 0; mt < 4; ++mt) {
                    mma_f16(c[mt][2 * ntp],     ah[mt], bb);
                    mma_f16(c[mt][2 * ntp + 1], ah[mt], bb + 2);
                }
            }
        }
        __syncthreads();
        if (t == 0 && ch + 2 < NCH) {
            FENCE_PROXY_ASYNC();
            MBARRIER_EXPECT_TX(sb + P_MB + s * 8, B_TILE_P);
            bulk_g2s(sb + PB0 + s * B_TILE_P, g_BP + (size_t)(ch + 2) * B_TILE_P, B_TILE_P, sb + P_MB + s * 8);
        }
    }

    // C -> smem (64 rows x 512 cols)
    float* Cs = (float*)smem;
#pragma unroll
    for (int mt = 0; mt < 4; ++mt)
#pragma unroll
        for (int nt = 0; nt < 8; ++nt) {
            int r  = mt * 16 + (lane >> 2);
            int c0 = wn * 64 + nt * 8 + (lane & 3) * 2;
            *(float2*)(Cs + r * CSTRIDE_P + c0)       = make_float2(c[mt][nt][0], c[mt][nt][1]);
            *(float2*)(Cs + (r + 8) * CSTRIDE_P + c0) = make_float2(c[mt][nt][2], c[mt][nt][3]);
        }
    __syncthreads();

    // epilogue: z = sum relu(C + U[src] + V[dst] + b1) * W2 ; out = sigmoid(z+b2)
    {
        int r = t >> 2, q = t & 3;
        const float*  crow = Cs + r * CSTRIDE_P + q * 128;
        const __half* urow = g_UVh + (size_t)ssrc[r] * (2 * H) + q * 128;
        const __half* vrow = g_UVh + (size_t)sdst[r] * (2 * H) + H + q * 128;
        float partial = 0.f;
#pragma unroll
        for (int j = 0; j < 128; j += 8) {
            float4 c0 = *(const float4*)(crow + j);
            float4 c1 = *(const float4*)(crow + j + 4);
            uint4 uu = *(const uint4*)(urow + j);
            uint4 vv = *(const uint4*)(vrow + j);
            float2 u0 = __half22float2(*reinterpret_cast<__half2*>(&uu.x));
            float2 u1 = __half22float2(*reinterpret_cast<__half2*>(&uu.y));
            float2 u2 = __half22float2(*reinterpret_cast<__half2*>(&uu.z));
            float2 u3 = __half22float2(*reinterpret_cast<__half2*>(&uu.w));
            float2 v0 = __half22float2(*reinterpret_cast<__half2*>(&vv.x));
            float2 v1 = __half22float2(*reinterpret_cast<__half2*>(&vv.y));
            float2 v2 = __half22float2(*reinterpret_cast<__half2*>(&vv.z));
            float2 v3 = __half22float2(*reinterpret_cast<__half2*>(&vv.w));
            int n = q * 128 + j;
            float h0 = c0.x + u0.x + v0.x + b1s[n + 0];
            float h1 = c0.y + u0.y + v0.y + b1s[n + 1];
            float h2 = c0.z + u1.x + v1.x + b1s[n + 2];
            float h3 = c0.w + u1.y + v1.y + b1s[n + 3];
            float h4 = c1.x + u2.x + v2.x + b1s[n + 4];
            float h5 = c1.y + u2.y + v2.y + b1s[n + 5];
            float h6 = c1.z + u3.x + v3.x + b1s[n + 6];
            float h7 = c1.w + u3.y + v3.y + b1s[n + 7];
            partial = fmaf(fmaxf(h0, 0.f), w2s[n + 0], partial);
            partial = fmaf(fmaxf(h1, 0.f), w2s[n + 1], partial);
            partial = fmaf(fmaxf(h2, 0.f), w2s[n + 2], partial);
            partial = fmaf(fmaxf(h3, 0.f), w2s[n + 3], partial);
            partial = fmaf(fmaxf(h4, 0.f), w2s[n + 4], partial);
            partial = fmaf(fmaxf(h5, 0.f), w2s[n + 5], partial);
            partial = fmaf(fmaxf(h6, 0.f), w2s[n + 6], partial);
            partial = fmaf(fmaxf(h7, 0.f), w2s[n + 7], partial);
        }
        partial += __shfl_xor_sync(0xffffffffu, partial, 1);
        partial += __shfl_xor_sync(0xffffffffu, partial, 2);
        if (q == 0) {
            float z = partial + b2[0];
            out[p0 + r] = 1.f / (1.f + expf(-z));
        }
    }
}

// ---------------- launch -----------------------------------------------------
extern "C" void kernel_launch(void* const* d_in, const int* in_sizes, int n_in,
                              void* d_out, int out_size) {
    const float* E   = (const float*)d_in[1];
    const int*   rel = (const int*)  d_in[2];
    const float* W1  = (const float*)d_in[3];
    const float* b1  = (const float*)d_in[4];
    const float* W2  = (const float*)d_in[5];
    const float* b2  = (const float*)d_in[6];
    float* out = (float*)d_out;

    cudaFuncSetAttribute(prep_BP16, cudaFuncAttributeMaxDynamicSharedMemorySize, B_TILE_P);
    cudaFuncSetAttribute(prep_BU16, cudaFuncAttributeMaxDynamicSharedMemorySize, B64);
    cudaFuncSetAttribute(uv_mma_k, cudaFuncAttributeMaxDynamicSharedMemorySize, SMEM_UV);
    cudaFuncSetAttribute(pair_mma_k, cudaFuncAttributeMaxDynamicSharedMemorySize, SMEM_PAIR);

    prep_BP16<<<NCH, 256, B_TILE_P>>>(W1);
    prep_BU16<<<dim3(NCH, 4), 256, B64>>>(W1);
    prep_ET16<<<dim3(NCH, 128), 256>>>(E);
    uv_mma_k<<<dim3(128, 4), 256, SMEM_UV>>>();
    pair_mma_k<<<NPAIRS / 64, 256, SMEM_PAIR>>>(E, rel, b1, W2, b2, out);
}

// round 16
// speedup vs baseline: 1.3631x; 1.0152x over previous
#include <cuda_runtime.h>
#include <cuda_bf16.h>
#include <cuda_fp16.h>
#include <math.h>
#include <stdint.h>

#define H        512
#define NDRONES  16384
#define NPAIRS   131072

#define NCH      8          // K chunks of 64 (pair)
#define A64      16384      // 128 rows x 64k fp16
#define B64      32768      // 256 rows x 64k fp16
#define STAGE_UV 98304      // per uv stage: 2xA64 + 2xB64 (K=128)
#define B_TILE_P 65536      // pair B: 512 rows x 64k fp16
#define BSLICE   8192       // per-warp B slice (64 rows x 128B)

// ---------------- device scratch ---------------------------------------------
__device__ __align__(128) char g_ET[(size_t)128 * NCH * A64];   // E fp16 tiles (16MB)
__device__ __align__(128) char g_BU[(size_t)4 * NCH * B64];     // ABcomb^T fp16 tiles (1MB)
__device__ __align__(128) char g_BP[(size_t)NCH * B_TILE_P];    // W1d^T fp16 tiles (512KB)
__device__ __half g_UVh[(size_t)NDRONES * 2 * H];               // fp16 [U|V] per drone (32MB)

// ---------------- helpers ----------------------------------------------------
__device__ __forceinline__ uint32_t smem_u32(const void* p) {
    uint32_t a;
    asm("{ .reg .u64 t; cvta.to.shared.u64 t, %1; cvt.u32.u64 %0, t; }" : "=r"(a) : "l"(p));
    return a;
}
#define SW128(o) ((o) ^ (((o) >> 3) & 0x70))

__device__ __forceinline__ void ldsm_x4(uint32_t* r, uint32_t addr) {
    asm volatile("ldmatrix.sync.aligned.m8n8.x4.shared.b16 {%0,%1,%2,%3}, [%4];"
        : "=r"(r[0]), "=r"(r[1]), "=r"(r[2]), "=r"(r[3]) : "r"(addr));
}
__device__ __forceinline__ void mma_f16(float* c, const uint32_t* a, const uint32_t* b) {
    asm volatile("mma.sync.aligned.m16n8k16.row.col.f32.f16.f16.f32 "
        "{%0,%1,%2,%3}, {%4,%5,%6,%7}, {%8,%9}, {%0,%1,%2,%3};"
        : "+f"(c[0]), "+f"(c[1]), "+f"(c[2]), "+f"(c[3])
        : "r"(a[0]), "r"(a[1]), "r"(a[2]), "r"(a[3]), "r"(b[0]), "r"(b[1]));
}

#define MBARRIER_INIT(mbar, cnt) \
    asm volatile("mbarrier.init.shared.b64 [%0], %1;" :: "r"((uint32_t)(mbar)), "r"((uint32_t)(cnt)) : "memory")
#define MBARRIER_EXPECT_TX(mbar, tx) \
    asm volatile("mbarrier.arrive.expect_tx.shared.b64 _, [%0], %1;" :: "r"((uint32_t)(mbar)), "r"((uint32_t)(tx)) : "memory")
#define MBARRIER_WAIT_PARITY(mbar, parity) do { \
    uint32_t _m = (uint32_t)(mbar); uint32_t _p = (uint32_t)(parity); uint32_t _d; \
    asm volatile("{\n\t.reg .pred p;\n\tmbarrier.try_wait.parity.acquire.cta.shared::cta.b64 p, [%1], %2;\n\tselp.b32 %0,1,0,p;\n\t}" \
        : "=r"(_d) : "r"(_m), "r"(_p) : "memory"); \
    if (!_d) { \
        asm volatile("{\n\t.reg .pred P1;\n\tWL_%=:\n\tmbarrier.try_wait.parity.acquire.cta.shared::cta.b64 P1, [%0], %1, 0x989680;\n\t@P1 bra.uni WD_%=;\n\tbra.uni WL_%=;\n\tWD_%=:\n\t}" \
            :: "r"(_m), "r"(_p) : "memory"); \
    } } while (0)
#define FENCE_PROXY_ASYNC() asm volatile("fence.proxy.async.shared::cta;" ::: "memory")

__device__ __forceinline__ void bulk_g2s(uint32_t dst, const void* src, uint32_t bytes, uint32_t mbar) {
    asm volatile("cp.async.bulk.shared::cluster.global.mbarrier::complete_tx::bytes [%0], [%1], %2, [%3];"
        :: "r"(dst), "l"(src), "r"(bytes), "r"(mbar) : "memory");
}

// ---------------- SMEM layouts -----------------------------------------------
// uv: 2 stages of 96KB at 0/98304; epilogue C (133120B) reuses from 0
#define UV_MB     196608
#define SMEM_UV   197120
#define CSTRIDE_U 260
// pair: A 2x8K at 0/8192, B 2x64K at 16384/81920; 16 slice mbarriers
#define PA0       0
#define PA1       8192
#define PB0       16384
#define P_MB      163840          // 2 stages x 8 slices x 8B = 128B
#define P_SRC     164032
#define P_DST     164288
#define P_B1      164544
#define P_W2      166592
#define SMEM_PAIR 168640
#define CSTRIDE_P 516

// ---------------- merged prep kernel (fp16) ----------------------------------
// grid x: [0,8) = BP chunks; [8,40) = BU (ch,nb); [40,1064) = ET (ch,mb)
__global__ void prep_all(const float* __restrict__ W1, const float* __restrict__ E) {
    extern __shared__ char bsm[];   // 64KB
    int t = threadIdx.x, bx = blockIdx.x;
    if (bx < 8) {               // ---- BP: 512 rows x 64k fp16 ----
        int ch = bx, k0 = ch * 64;
#pragma unroll
        for (int rr = 0; rr < 2; ++rr) {
            int n = rr * 256 + t;
#pragma unroll 4
            for (int i = 0; i < 64; ++i) {
                float v = W1[(size_t)(3 * H + k0 + i) * H + n];
                *(__half*)(bsm + SW128((uint32_t)(n * 128 + i * 2))) = __float2half_rn(v);
            }
        }
        __syncthreads();
        uint4* dst = (uint4*)(g_BP + (size_t)ch * B_TILE_P);
        const uint4* s4 = (const uint4*)bsm;
#pragma unroll
        for (int j = 0; j < 16; ++j) dst[t * 16 + j] = s4[t * 16 + j];
    } else if (bx < 40) {       // ---- BU: 256 rows x 64k fp16 ----
        int idx = bx - 8, ch = idx & 7, nb = idx >> 3;
        int k0 = ch * 64;
        int ng = nb * 256 + t;
        bool isv = ng >= H;
        int nn = ng & (H - 1);
#pragma unroll 4
        for (int i = 0; i < 64; ++i) {
            int k = k0 + i;
            float wc = W1[(size_t)(2 * H + k) * H + nn];
            float v = isv ? (W1[(size_t)(H + k) * H + nn] + wc)
                          : (W1[(size_t)k * H + nn] - wc);
            *(__half*)(bsm + SW128((uint32_t)(t * 128 + i * 2))) = __float2half_rn(v);
        }
        __syncthreads();
        uint4* dst = (uint4*)(g_BU + ((size_t)nb * NCH + ch) * B64);
        const uint4* s4 = (const uint4*)bsm;
#pragma unroll
        for (int j = 0; j < 8; ++j) dst[t * 8 + j] = s4[t * 8 + j];
    } else {                    // ---- ET: 128 rows x 64k fp16 ----
        int idx = bx - 40, ch = idx & 7, mb = idx >> 3;
        int k0 = ch * 64, m0 = mb * 128;
#pragma unroll 4
        for (int i = 0; i < 32; ++i) {
            int id2 = i * 256 + t;
            int k_l = id2 & 63, r = id2 >> 6;
            float v = E[(size_t)(m0 + r) * H + k0 + k_l];
            *(__half*)(bsm + SW128((uint32_t)(r * 128 + k_l * 2))) = __float2half_rn(v);
        }
        __syncthreads();
        uint4* dst = (uint4*)(g_ET + ((size_t)mb * NCH + ch) * A64);
        const uint4* s4 = (const uint4*)bsm;
#pragma unroll
        for (int j = 0; j < 4; ++j) dst[t * 4 + j] = s4[t * 4 + j];
    }
}

// ---------------- UV GEMM: K-chunk 128 + fp16 writeback (R15, unchanged) -----
__global__ void __launch_bounds__(256, 1) uv_mma_k() {
    extern __shared__ __align__(1024) char smem[];
    uint32_t sb = smem_u32(smem);
    int t = threadIdx.x, lane = t & 31, w = t >> 5;
    int wm = w >> 2, wn = w & 3;          // warp tile 64x64
    int mb = blockIdx.x, nb = blockIdx.y;

    if (t == 0) { MBARRIER_INIT(sb + UV_MB, 1); MBARRIER_INIT(sb + UV_MB + 8, 1); }
    __syncthreads();
    const char* gA = g_ET + (size_t)mb * NCH * A64;
    const char* gB = g_BU + (size_t)nb * NCH * B64;
    if (t == 0) {
#pragma unroll
        for (int s = 0; s < 2; ++s) {
            int cc = 2 * s;
            MBARRIER_EXPECT_TX(sb + UV_MB + s * 8, STAGE_UV);
            bulk_g2s(sb + s * STAGE_UV,          gA + (size_t)cc * A64,        A64, sb + UV_MB + s * 8);
            bulk_g2s(sb + s * STAGE_UV + A64,    gA + (size_t)(cc + 1) * A64,  A64, sb + UV_MB + s * 8);
            bulk_g2s(sb + s * STAGE_UV + 32768,  gB + (size_t)cc * B64,        B64, sb + UV_MB + s * 8);
            bulk_g2s(sb + s * STAGE_UV + 65536,  gB + (size_t)(cc + 1) * B64,  B64, sb + UV_MB + s * 8);
        }
    }

    uint32_t arx = (lane & 7) * 16, selA = (lane >> 4) * 16;
    uint32_t brx = (lane & 7) * 16, selB = ((lane >> 3) & 1) * 16;
    uint32_t aoff[4];
#pragma unroll
    for (int mt = 0; mt < 4; ++mt)
        aoff[mt] = (uint32_t)(wm * 64 + mt * 16 + (lane & 15)) * 128;
    uint32_t boffB = (uint32_t)(wn * 64 + ((lane >> 4) & 1) * 8 + (lane & 7)) * 128;

    float c[4][8][4];
#pragma unroll
    for (int a = 0; a < 4; ++a)
#pragma unroll
        for (int b = 0; b < 8; ++b)
#pragma unroll
            for (int d = 0; d < 4; ++d) c[a][b][d] = 0.f;

    int ph0 = 0, ph1 = 0;
    for (int c2 = 0; c2 < 4; ++c2) {
        int s = c2 & 1;
        if (s == 0) { MBARRIER_WAIT_PARITY(sb + UV_MB, ph0); ph0 ^= 1; }
        else        { MBARRIER_WAIT_PARITY(sb + UV_MB + 8, ph1); ph1 ^= 1; }
#pragma unroll
        for (int half = 0; half < 2; ++half) {
            uint32_t As = sb + s * STAGE_UV + half * A64;
            uint32_t Bs = sb + s * STAGE_UV + 32768 + half * B64;
#pragma unroll
            for (int kh = 0; kh < 4; ++kh) {
                uint32_t kk = kh * 32;
                uint32_t ah[4][4];
#pragma unroll
                for (int mt = 0; mt < 4; ++mt)
                    ldsm_x4(ah[mt], As + aoff[mt] + ((kk + selA) ^ arx));
#pragma unroll
                for (int ntp = 0; ntp < 4; ++ntp) {
                    uint32_t bb[4];
                    ldsm_x4(bb, Bs + boffB + ntp * 2048 + ((kk + selB) ^ brx));
#pragma unroll
                    for (int mt = 0; mt < 4; ++mt) {
                        mma_f16(c[mt][2 * ntp],     ah[mt], bb);
                        mma_f16(c[mt][2 * ntp + 1], ah[mt], bb + 2);
                    }
                }
            }
        }
        __syncthreads();
        if (t == 0 && c2 + 2 < 4) {
            FENCE_PROXY_ASYNC();
            int cc = 2 * (c2 + 2);
            MBARRIER_EXPECT_TX(sb + UV_MB + s * 8, STAGE_UV);
            bulk_g2s(sb + s * STAGE_UV,          gA + (size_t)cc * A64,        A64, sb + UV_MB + s * 8);
            bulk_g2s(sb + s * STAGE_UV + A64,    gA + (size_t)(cc + 1) * A64,  A64, sb + UV_MB + s * 8);
            bulk_g2s(sb + s * STAGE_UV + 32768,  gB + (size_t)cc * B64,        B64, sb + UV_MB + s * 8);
            bulk_g2s(sb + s * STAGE_UV + 65536,  gB + (size_t)(cc + 1) * B64,  B64, sb + UV_MB + s * 8);
        }
    }

    float* Cs = (float*)smem;
#pragma unroll
    for (int mt = 0; mt < 4; ++mt)
#pragma unroll
        for (int nt = 0; nt < 8; ++nt) {
            int r  = wm * 64 + mt * 16 + (lane >> 2);
            int c0 = wn * 64 + nt * 8 + (lane & 3) * 2;
            *(float2*)(Cs + r * CSTRIDE_U + c0)       = make_float2(c[mt][nt][0], c[mt][nt][1]);
            *(float2*)(Cs + (r + 8) * CSTRIDE_U + c0) = make_float2(c[mt][nt][2], c[mt][nt][3]);
        }
    __syncthreads();
    int r = t >> 1, half = t & 1;
    __half* dst = g_UVh + (size_t)(mb * 128 + r) * (2 * H) + nb * 256 + half * 128;
    const float* srow = Cs + r * CSTRIDE_U + half * 128;
#pragma unroll
    for (int j = 0; j < 128; j += 8) {
        float4 a = *(const float4*)(srow + j);
        float4 b = *(const float4*)(srow + j + 4);
        __half2 h0 = __floats2half2_rn(a.x, a.y);
        __half2 h1 = __floats2half2_rn(a.z, a.w);
        __half2 h2 = __floats2half2_rn(b.x, b.y);
        __half2 h3 = __floats2half2_rn(b.z, b.w);
        *(uint4*)(dst + j) = make_uint4(
            *reinterpret_cast<uint32_t*>(&h0), *reinterpret_cast<uint32_t*>(&h1),
            *reinterpret_cast<uint32_t*>(&h2), *reinterpret_cast<uint32_t*>(&h3));
    }
}

// ---------------- pair GEMM: R15 structure + per-warp B slice barriers -------
__global__ void __launch_bounds__(256, 1) pair_mma_k(
    const float* __restrict__ E, const int* __restrict__ rel,
    const float* __restrict__ b1, const float* __restrict__ W2,
    const float* __restrict__ b2, float* __restrict__ out)
{
    extern __shared__ __align__(1024) char smem[];
    uint32_t sb = smem_u32(smem);
    int t = threadIdx.x, lane = t & 31, w = t >> 5;       // w 0..7
    int wn = w;                                           // 1x8 grid, warp tile 64x64
    int bx = blockIdx.x;
    int p0 = bx * 64;

    int* ssrc = (int*)(smem + P_SRC);
    int* sdst = (int*)(smem + P_DST);
    float* b1s = (float*)(smem + P_B1);
    float* w2s = (float*)(smem + P_W2);
    if (t < 64) {
        ssrc[t] = rel[(size_t)(p0 + t) * 2 + 0];
        sdst[t] = rel[(size_t)(p0 + t) * 2 + 1];
    }
    b1s[t] = b1[t];       b1s[256 + t] = b1[256 + t];
    w2s[t] = W2[t];       w2s[256 + t] = W2[256 + t];
    if (t < 16)
        MBARRIER_INIT(sb + P_MB + t * 8, 1);   // 2 stages x 8 slices
    __syncthreads();

    // initial fills: stage 0/1 = chunks 0/1, sliced per warp (8x8KB each)
    if (t == 0) {
#pragma unroll
        for (int s = 0; s < 2; ++s)
#pragma unroll
            for (int sl = 0; sl < 8; ++sl) {
                uint32_t mb = sb + P_MB + (s * 8 + sl) * 8;
                MBARRIER_EXPECT_TX(mb, BSLICE);
                bulk_g2s(sb + PB0 + s * B_TILE_P + sl * BSLICE,
                         g_BP + (size_t)s * B_TILE_P + sl * BSLICE, BSLICE, mb);
            }
    }

    // line-coalesced gather: 16 lanes per row, 4 passes (R13-verified).
    int row16 = t >> 4, seg = t & 15;
    const float* Sp[4];
    const float* Dp[4];
    uint32_t asw[4];
#pragma unroll
    for (int pass = 0; pass < 4; ++pass) {
        int r = pass * 16 + row16;
        Sp[pass] = E + (size_t)ssrc[r] * H + seg * 4;
        Dp[pass] = E + (size_t)sdst[r] * H + seg * 4;
        asw[pass] = SW128((uint32_t)(r * 128 + seg * 8));
    }

    uint32_t arx = (lane & 7) * 16, selA = (lane >> 4) * 16;
    uint32_t brx = (lane & 7) * 16, selB = ((lane >> 3) & 1) * 16;
    uint32_t aoff[4];
#pragma unroll
    for (int mt = 0; mt < 4; ++mt)
        aoff[mt] = (uint32_t)(mt * 16 + (lane & 15)) * 128;          // M=64: 4 tiles of 16
    uint32_t boffB = (uint32_t)(wn * 64 + ((lane >> 4) & 1) * 8 + (lane & 7)) * 128;
    uint32_t mySlice = sb + P_MB + wn * 8;   // + s*64 for stage

    float c[4][8][4];
#pragma unroll
    for (int a = 0; a < 4; ++a)
#pragma unroll
        for (int b = 0; b < 8; ++b)
#pragma unroll
            for (int d = 0; d < 4; ++d) c[a][b][d] = 0.f;

    // prefetch chunk 0: one float4 per matrix per pass
    float4 ps[4], pd[4];
#pragma unroll
    for (int j = 0; j < 4; ++j) {
        ps[j] = *(const float4*)(Sp[j]);
        pd[j] = *(const float4*)(Dp[j]);
    }

    int ph0 = 0, ph1 = 0;
    for (int ch = 0; ch < NCH; ++ch) {
        int s = ch & 1;
        // ---- stage A(ch) from prefetched regs: single fp16, STS.64 ----
        {
            char* Ab = smem + (s ? PA1 : PA0);
#pragma unroll
            for (int j = 0; j < 4; ++j) {
                float pr0 = ps[j].x * pd[j].x;
                float pr1 = ps[j].y * pd[j].y;
                float pr2 = ps[j].z * pd[j].z;
                float pr3 = ps[j].w * pd[j].w;
                __half2 h0 = __floats2half2_rn(pr0, pr1);
                __half2 h1 = __floats2half2_rn(pr2, pr3);
                *(uint2*)(Ab + asw[j]) = make_uint2(
                    *reinterpret_cast<uint32_t*>(&h0), *reinterpret_cast<uint32_t*>(&h1));
            }
        }
        // ---- prefetch chunk ch+1 (hidden under MMA) ----
        if (ch + 1 < NCH) {
            int k0 = (ch + 1) * 64;
#pragma unroll
            for (int j = 0; j < 4; ++j) {
                ps[j] = *(const float4*)(Sp[j] + k0);
                pd[j] = *(const float4*)(Dp[j] + k0);
            }
        }
        // ---- wait ONLY this warp's B slice, then CTA sync for A ----
        if (s == 0) { MBARRIER_WAIT_PARITY(mySlice, ph0); ph0 ^= 1; }
        else        { MBARRIER_WAIT_PARITY(mySlice + 64, ph1); ph1 ^= 1; }
        __syncthreads();
        // ---- MMA(ch): single term, warp tile 64x64 ----
        uint32_t As = sb + (s ? PA1 : PA0);
        uint32_t Bs = sb + PB0 + s * B_TILE_P;
#pragma unroll
        for (int kh = 0; kh < 4; ++kh) {
            uint32_t kk = kh * 32;
            uint32_t ah[4][4];
#pragma unroll
            for (int mt = 0; mt < 4; ++mt)
                ldsm_x4(ah[mt], As + aoff[mt] + ((kk + selA) ^ arx));
#pragma unroll
            for (int ntp = 0; ntp < 4; ++ntp) {
                uint32_t bb[4];
                ldsm_x4(bb, Bs + boffB + ntp * 2048 + ((kk + selB) ^ brx));
#pragma unroll
                for (int mt = 0; mt < 4; ++mt) {
                    mma_f16(c[mt][2 * ntp],     ah[mt], bb);
                    mma_f16(c[mt][2 * ntp + 1], ah[mt], bb + 2);
                }
            }
        }
        __syncthreads();
        if (t == 0 && ch + 2 < NCH) {
            FENCE_PROXY_ASYNC();
#pragma unroll
            for (int sl = 0; sl < 8; ++sl) {
                uint32_t mb = sb + P_MB + (s * 8 + sl) * 8;
                MBARRIER_EXPECT_TX(mb, BSLICE);
                bulk_g2s(sb + PB0 + s * B_TILE_P + sl * BSLICE,
                         g_BP + (size_t)(ch + 2) * B_TILE_P + sl * BSLICE, BSLICE, mb);
            }
        }
    }

    // C -> smem (64 rows x 512 cols)
    float* Cs = (float*)smem;
#pragma unroll
    for (int mt = 0; mt < 4; ++mt)
#pragma unroll
        for (int nt = 0; nt < 8; ++nt) {
            int r  = mt * 16 + (lane >> 2);
            int c0 = wn * 64 + nt * 8 + (lane & 3) * 2;
            *(float2*)(Cs + r * CSTRIDE_P + c0)       = make_float2(c[mt][nt][0], c[mt][nt][1]);
            *(float2*)(Cs + (r + 8) * CSTRIDE_P + c0) = make_float2(c[mt][nt][2], c[mt][nt][3]);
        }
    __syncthreads();

    // epilogue: z = sum relu(C + U[src] + V[dst] + b1) * W2 ; out = sigmoid(z+b2)
    {
        int r = t >> 2, q = t & 3;
        const float*  crow = Cs + r * CSTRIDE_P + q * 128;
        const __half* urow = g_UVh + (size_t)ssrc[r] * (2 * H) + q * 128;
        const __half* vrow = g_UVh + (size_t)sdst[r] * (2 * H) + H + q * 128;
        float partial = 0.f;
#pragma unroll
        for (int j = 0; j < 128; j += 8) {
            float4 c0 = *(const float4*)(crow + j);
            float4 c1 = *(const float4*)(crow + j + 4);
            uint4 uu = *(const uint4*)(urow + j);
            uint4 vv = *(const uint4*)(vrow + j);
            float2 u0 = __half22float2(*reinterpret_cast<__half2*>(&uu.x));
            float2 u1 = __half22float2(*reinterpret_cast<__half2*>(&uu.y));
            float2 u2 = __half22float2(*reinterpret_cast<__half2*>(&uu.z));
            float2 u3 = __half22float2(*reinterpret_cast<__half2*>(&uu.w));
            float2 v0 = __half22float2(*reinterpret_cast<__half2*>(&vv.x));
            float2 v1 = __half22float2(*reinterpret_cast<__half2*>(&vv.y));
            float2 v2 = __half22float2(*reinterpret_cast<__half2*>(&vv.z));
            float2 v3 = __half22float2(*reinterpret_cast<__half2*>(&vv.w));
            int n = q * 128 + j;
            float h0 = c0.x + u0.x + v0.x + b1s[n + 0];
            float h1 = c0.y + u0.y + v0.y + b1s[n + 1];
            float h2 = c0.z + u1.x + v1.x + b1s[n + 2];
            float h3 = c0.w + u1.y + v1.y + b1s[n + 3];
            float h4 = c1.x + u2.x + v2.x + b1s[n + 4];
            float h5 = c1.y + u2.y + v2.y + b1s[n + 5];
            float h6 = c1.z + u3.x + v3.x + b1s[n + 6];
            float h7 = c1.w + u3.y + v3.y + b1s[n + 7];
            partial = fmaf(fmaxf(h0, 0.f), w2s[n + 0], partial);
            partial = fmaf(fmaxf(h1, 0.f), w2s[n + 1], partial);
            partial = fmaf(fmaxf(h2, 0.f), w2s[n + 2], partial);
            partial = fmaf(fmaxf(h3, 0.f), w2s[n + 3], partial);
            partial = fmaf(fmaxf(h4, 0.f), w2s[n + 4], partial);
            partial = fmaf(fmaxf(h5, 0.f), w2s[n + 5], partial);
            partial = fmaf(fmaxf(h6, 0.f), w2s[n + 6], partial);
            partial = fmaf(fmaxf(h7, 0.f), w2s[n + 7], partial);
        }
        partial += __shfl_xor_sync(0xffffffffu, partial, 1);
        partial += __shfl_xor_sync(0xffffffffu, partial, 2);
        if (q == 0) {
            float z = partial + b2[0];
            out[p0 + r] = 1.f / (1.f + expf(-z));
        }
    }
}

// ---------------- launch -----------------------------------------------------
extern "C" void kernel_launch(void* const* d_in, const int* in_sizes, int n_in,
                              void* d_out, int out_size) {
    const float* E   = (const float*)d_in[1];
    const int*   rel = (const int*)  d_in[2];
    const float* W1  = (const float*)d_in[3];
    const float* b1  = (const float*)d_in[4];
    const float* W2  = (const float*)d_in[5];
    const float* b2  = (const float*)d_in[6];
    float* out = (float*)d_out;

    cudaFuncSetAttribute(prep_all, cudaFuncAttributeMaxDynamicSharedMemorySize, B_TILE_P);
    cudaFuncSetAttribute(uv_mma_k, cudaFuncAttributeMaxDynamicSharedMemorySize, SMEM_UV);
    cudaFuncSetAttribute(pair_mma_k, cudaFuncAttributeMaxDynamicSharedMemorySize, SMEM_PAIR);

    prep_all<<<1064, 256, B_TILE_P>>>(W1, E);
    uv_mma_k<<<dim3(128, 4), 256, SMEM_UV>>>();
    pair_mma_k<<<NPAIRS / 64, 256, SMEM_PAIR>>>(E, rel, b1, W2, b2, out);
}